// round 13
// baseline (speedup 1.0000x reference)
#include <cuda_runtime.h>
#include <cuda_bf16.h>
#include <math.h>
#include <cstdint>

#define TOK 4096      // B*S
#define HID 4096
#define SEQ 2048
#define NHEAD 32
#define HDIM 128

// ---------------- scratch (allocation-free: __device__ globals) ----------------
__device__ float g_Q[TOK * HID];
__device__ float g_K[TOK * HID];
__device__ float g_V[TOK * HID];
__device__ float g_C[TOK * HID];
__device__ float g_cos[SEQ * 64];
__device__ float g_sin[SEQ * 64];
__device__ __nv_bfloat16 g_Ahi[TOK * HID];   // split of X (then of C)
__device__ __nv_bfloat16 g_Alo[TOK * HID];
__device__ __nv_bfloat16 g_Whi[HID * HID];   // split of current weight
__device__ __nv_bfloat16 g_Wlo[HID * HID];

typedef unsigned long long ull;
__device__ __forceinline__ uint32_t smem_u32(const void* p) {
    uint32_t a;
    asm("{ .reg .u64 t; cvta.to.shared.u64 t, %1; cvt.u32.u64 %0, t; }" : "=r"(a) : "l"(p));
    return a;
}
__device__ __forceinline__ void cp16(uint32_t s, const void* g) {
    asm volatile("cp.async.cg.shared.global [%0], [%1], 16;" :: "r"(s), "l"(g));
}
__device__ __forceinline__ void ldsm_x4(uint32_t* r, uint32_t addr) {
    asm volatile("ldmatrix.sync.aligned.m8n8.x4.shared.b16 {%0,%1,%2,%3}, [%4];"
                 : "=r"(r[0]), "=r"(r[1]), "=r"(r[2]), "=r"(r[3]) : "r"(addr));
}
__device__ __forceinline__ void mma_bf16(float* d, const uint32_t* a, const uint32_t* b) {
    asm volatile("mma.sync.aligned.m16n8k16.row.col.f32.bf16.bf16.f32 "
                 "{%0,%1,%2,%3}, {%4,%5,%6,%7}, {%8,%9}, {%0,%1,%2,%3};"
                 : "+f"(d[0]), "+f"(d[1]), "+f"(d[2]), "+f"(d[3])
                 : "r"(a[0]), "r"(a[1]), "r"(a[2]), "r"(a[3]), "r"(b[0]), "r"(b[1]));
}

// ---------------- fp32 split: x -> hi(bf16) + lo(bf16 residual), 4 elem/thread --
__global__ void split_kernel(const float* __restrict__ x,
                             __nv_bfloat16* __restrict__ hi,
                             __nv_bfloat16* __restrict__ lo, int n4) {
    int i = blockIdx.x * blockDim.x + threadIdx.x;
    if (i >= n4) return;
    float4 v = *reinterpret_cast<const float4*>(x + 4 * (size_t)i);
    __nv_bfloat16 h0 = __float2bfloat16(v.x), h1 = __float2bfloat16(v.y);
    __nv_bfloat16 h2 = __float2bfloat16(v.z), h3 = __float2bfloat16(v.w);
    __nv_bfloat162 hp0(h0, h1), hp1(h2, h3);
    __nv_bfloat162 lp0(__float2bfloat16(v.x - __bfloat162float(h0)),
                       __float2bfloat16(v.y - __bfloat162float(h1)));
    __nv_bfloat162 lp1(__float2bfloat16(v.z - __bfloat162float(h2)),
                       __float2bfloat16(v.w - __bfloat162float(h3)));
    *reinterpret_cast<uint2*>(hi + 4 * (size_t)i) =
        make_uint2(*(uint32_t*)&hp0, *(uint32_t*)&hp1);
    *reinterpret_cast<uint2*>(lo + 4 * (size_t)i) =
        make_uint2(*(uint32_t*)&lp0, *(uint32_t*)&lp1);
}

// ---------------- HMMA GEMM: C[t][o] = sum_k A[t][k]*W[o][k] -------------------
// 128x128 CTA tile, BK=64, 16 warps (32x32 each) = 4 warps/SMSP for latency
// hiding. mma.m16n8k16 bf16, split-3 products into fp32 accumulators.
// B fragments via ldmatrix.x4 (n16 per load). One __syncthreads per iteration.
#define BK 64
#define TPITCH 144                         // bytes per smem row (128 data + 16 pad)
#define TILE_B (128 * TPITCH)              // 18432
#define BUF_B (4 * TILE_B)                 // Ahi,Alo,Bhi,Blo = 73728
#define GEMM_SMEM (2 * BUF_B)              // 147456
#define NKIT (HID / BK)                    // 64
#define NPID 32
#define GROUP_M 12

__global__ __launch_bounds__(512, 1)
void gemm_hmma(const __nv_bfloat16* __restrict__ Ahi, const __nv_bfloat16* __restrict__ Alo,
               const __nv_bfloat16* __restrict__ Bhi, const __nv_bfloat16* __restrict__ Blo,
               float* __restrict__ C) {
    extern __shared__ __align__(128) char smem[];
    const uint32_t smem_base = smem_u32(smem);
    const int tid = threadIdx.x;
    const int wid = tid >> 5, lane = tid & 31;

    // grouped swizzle: consecutive pids walk 12 bm-rows before advancing bn
    const int pid = blockIdx.y * NPID + blockIdx.x;
    const int group_id = pid / (GROUP_M * NPID);
    const int first_m = group_id * GROUP_M;
    const int gsz = (NPID - first_m) < GROUP_M ? (NPID - first_m) : GROUP_M;
    const int bm = (first_m + (pid % gsz)) << 7;
    const int bn = ((pid % (GROUP_M * NPID)) / gsz) << 7;

    const __nv_bfloat16* src[4] = {Ahi + (size_t)bm * HID, Alo + (size_t)bm * HID,
                                   Bhi + (size_t)bn * HID, Blo + (size_t)bn * HID};

    const int m_base = (wid & 3) << 5;     // 0,32,64,96
    const int n_base = (wid >> 2) << 5;    // 0,32,64,96

    float acc[2][4][4];
#pragma unroll
    for (int mi = 0; mi < 2; mi++)
#pragma unroll
        for (int ni = 0; ni < 4; ni++)
#pragma unroll
            for (int q = 0; q < 4; q++) acc[mi][ni][q] = 0.f;

    // loader: 4096 16B units per chunk (4 tiles x 128 rows x 8 units), 8/thread
#define LOAD_CHUNK(bufsel, k0)                                                   \
    do {                                                                         \
        uint32_t sb = smem_base + (bufsel) * BUF_B;                              \
        _Pragma("unroll")                                                        \
        for (int u = 0; u < 8; u++) {                                            \
            int e = (u << 9) + tid;                                              \
            int t = e >> 10, r = (e >> 3) & 127, q = e & 7;                      \
            cp16(sb + t * TILE_B + r * TPITCH + q * 16,                          \
                 src[t] + (size_t)r * HID + (k0) + q * 8);                       \
        }                                                                        \
    } while (0)

    LOAD_CHUNK(0, 0);
    asm volatile("cp.async.commit_group;");

    // A ldsm.x4: rows m16, two 16B col halves
    const uint32_t aoff = (m_base + (lane & 15)) * TPITCH + ((lane >> 4) << 4);
    // B ldsm.x4: tiles {n0-7,k0-7},{n0-7,k8-15},{n8-15,k0-7},{n8-15,k8-15}
    const uint32_t boff = (n_base + (lane & 7) + (((lane >> 4) & 1) << 3)) * TPITCH +
                          (((lane >> 3) & 1) << 4);

    int buf = 0;
    for (int it = 0; it < NKIT; it++) {
        asm volatile("cp.async.wait_group 0;");
        __syncthreads();
        if (it + 1 < NKIT) {
            LOAD_CHUNK(buf ^ 1, (it + 1) << 6);
            asm volatile("cp.async.commit_group;");
        }

        const uint32_t sA = smem_base + buf * BUF_B;
        const uint32_t sAhi = sA, sAlo = sA + TILE_B;
        const uint32_t sBhi = sA + 2 * TILE_B, sBlo = sA + 3 * TILE_B;
#pragma unroll
        for (int kk = 0; kk < 4; kk++) {   // four k16 steps per 64-chunk
            uint32_t ah[2][4], al[2][4], bh[2][4], bl[2][4];
#pragma unroll
            for (int mi = 0; mi < 2; mi++) {
                ldsm_x4(ah[mi], sAhi + aoff + mi * (16 * TPITCH) + kk * 32);
                ldsm_x4(al[mi], sAlo + aoff + mi * (16 * TPITCH) + kk * 32);
            }
#pragma unroll
            for (int g = 0; g < 2; g++) {  // n16 groups
                ldsm_x4(bh[g], sBhi + boff + g * (16 * TPITCH) + kk * 32);
                ldsm_x4(bl[g], sBlo + boff + g * (16 * TPITCH) + kk * 32);
            }
#pragma unroll
            for (int mi = 0; mi < 2; mi++)
#pragma unroll
                for (int ni = 0; ni < 4; ni++) {
                    const uint32_t* bhp = &bh[ni >> 1][(ni & 1) << 1];
                    const uint32_t* blp = &bl[ni >> 1][(ni & 1) << 1];
                    mma_bf16(acc[mi][ni], ah[mi], bhp);
                    mma_bf16(acc[mi][ni], ah[mi], blp);
                    mma_bf16(acc[mi][ni], al[mi], bhp);
                }
        }
        buf ^= 1;
    }
#undef LOAD_CHUNK

    // epilogue: standard m16n8 accumulator thread mapping
#pragma unroll
    for (int mi = 0; mi < 2; mi++)
#pragma unroll
        for (int ni = 0; ni < 4; ni++) {
            int row = bm + m_base + mi * 16 + (lane >> 2);
            int col = bn + n_base + ni * 8 + ((lane & 3) << 1);
            *(float2*)&C[(size_t)row * HID + col] =
                make_float2(acc[mi][ni][0], acc[mi][ni][1]);
            *(float2*)&C[(size_t)(row + 8) * HID + col] =
                make_float2(acc[mi][ni][2], acc[mi][ni][3]);
        }
}

// ---------------- RoPE tables (double precision) -------------------------------
__global__ void rope_tables_kernel() {
    int i = blockIdx.x * blockDim.x + threadIdx.x;
    if (i >= SEQ * 64) return;
    int d = i & 63, s = i >> 6;
    double inv = exp(-((double)d / 64.0) * 9.210340371976184);  // ln(10000)
    double ang = (double)s * inv;
    g_cos[i] = (float)cos(ang);
    g_sin[i] = (float)sin(ang);
}

// ---------------- RoPE apply (in-place on Q and K), float2-vectorized ----------
__global__ void rope_apply_kernel() {
    int idx = blockIdx.x * blockDim.x + threadIdx.x;
    if (idx >= TOK * NHEAD * 32) return;
    int dp = (idx & 31) << 1;
    int head = (idx >> 5) & 31;
    int t = idx >> 10;
    int s = t & (SEQ - 1);
    float2 c = *(const float2*)&g_cos[(s << 6) + dp];
    float2 sn = *(const float2*)&g_sin[(s << 6) + dp];
    float* qp = g_Q + (size_t)t * HID + head * HDIM + dp;
    float* kp = g_K + (size_t)t * HID + head * HDIM + dp;
    float2 q1 = *(float2*)qp, q2 = *(float2*)(qp + 64);
    *(float2*)qp = make_float2(q1.x * c.x - q2.x * sn.x, q1.y * c.y - q2.y * sn.y);
    *(float2*)(qp + 64) = make_float2(q2.x * c.x + q1.x * sn.x, q2.y * c.y + q1.y * sn.y);
    float2 k1 = *(float2*)kp, k2 = *(float2*)(kp + 64);
    *(float2*)kp = make_float2(k1.x * c.x - k2.x * sn.x, k1.y * c.y - k2.y * sn.y);
    *(float2*)(kp + 64) = make_float2(k2.x * c.x + k1.x * sn.x, k2.y * c.y + k1.y * sn.y);
}

// ---------------- packed f32x2 helpers ----------------
__device__ __forceinline__ ull pk2(float x) {
    ull r; asm("mov.b64 %0, {%1, %1};" : "=l"(r) : "f"(x)); return r;
}
__device__ __forceinline__ float2 unpk(ull u) {
    float2 r; asm("mov.b64 {%0, %1}, %2;" : "=f"(r.x), "=f"(r.y) : "l"(u)); return r;
}
__device__ __forceinline__ void fma2(ull& d, ull a, ull b) {
    asm("fma.rn.f32x2 %0, %1, %2, %0;" : "+l"(d) : "l"(a), "l"(b));
}
__device__ __forceinline__ void mul2(ull& d, ull s) {
    asm("mul.rn.f32x2 %0, %0, %1;" : "+l"(d) : "l"(s));
}

// ---------------- Flash attention (causal, fp32, online softmax) ---------------
#define ATTN_SMEM (3 * 64 * 132 * 4)

__global__ __launch_bounds__(256, 2)
void flash_attn_kernel() {
    extern __shared__ __align__(16) float sm[];
    float* Qs = sm;
    float* Ks = sm + 64 * 132;
    float* Vs = sm + 2 * 64 * 132;
    float* Ps = Ks;   // overlay on Ks (K dead post-QK^T)

    const int qi = 31 - blockIdx.x;  // LPT
    const int head = blockIdx.y, b = blockIdx.z;
    const int tid = threadIdx.x;
    const int tx = tid & 15, ty = tid >> 4;
    const int r0 = ty << 2;
    const int tok0 = (b << 11) + (qi << 6);

    const float* Qg = g_Q + (size_t)tok0 * HID + head * HDIM;
    for (int f = tid; f < 64 * 32; f += 256) {
        int row = f >> 5, c4 = (f & 31) << 2;
        *(float4*)&Qs[row * 132 + c4] = *(const float4*)(Qg + (size_t)row * HID + c4);
    }

    float m[4], l[4];
    ull o2[4][4];
#pragma unroll
    for (int i = 0; i < 4; i++) {
        m[i] = -1e30f; l[i] = 0.f;
#pragma unroll
        for (int j = 0; j < 4; j++) o2[i][j] = 0ull;
    }
    __syncthreads();

    const float scale = 0.08838834764831845f;
    for (int kt = 0; kt <= qi; kt++) {
        const size_t kvoff = (size_t)((b << 11) + (kt << 6)) * HID + head * HDIM;
        for (int f = tid; f < 64 * 32; f += 256) {
            int row = f >> 5, c4 = (f & 31) << 2;
            *(float4*)&Ks[row * 132 + c4] = *(const float4*)(g_K + kvoff + (size_t)row * HID + c4);
            *(float4*)&Vs[row * 132 + c4] = *(const float4*)(g_V + kvoff + (size_t)row * HID + c4);
        }
        __syncthreads();

        ull s2[4][4];
#pragma unroll
        for (int i = 0; i < 4; i++)
#pragma unroll
            for (int j = 0; j < 4; j++) s2[i][j] = 0ull;

        for (int kk = 0; kk < 128; kk += 2) {
            ull qa[4], kb[4];
#pragma unroll
            for (int i = 0; i < 4; i++) qa[i] = *(const ull*)&Qs[(r0 + i) * 132 + kk];
#pragma unroll
            for (int j = 0; j < 4; j++) kb[j] = *(const ull*)&Ks[(tx + (j << 4)) * 132 + kk];
#pragma unroll
            for (int i = 0; i < 4; i++)
#pragma unroll
                for (int j = 0; j < 4; j++) fma2(s2[i][j], qa[i], kb[j]);
        }
        float sc[4][4];
#pragma unroll
        for (int i = 0; i < 4; i++)
#pragma unroll
            for (int j = 0; j < 4; j++) {
                float2 p = unpk(s2[i][j]);
                sc[i][j] = (p.x + p.y) * scale;
            }
        if (kt == qi) {
#pragma unroll
            for (int i = 0; i < 4; i++)
#pragma unroll
                for (int j = 0; j < 4; j++)
                    if (tx + (j << 4) > r0 + i) sc[i][j] = -1e9f;
        }
        __syncthreads();

#pragma unroll
        for (int i = 0; i < 4; i++) {
            float v = fmaxf(fmaxf(sc[i][0], sc[i][1]), fmaxf(sc[i][2], sc[i][3]));
#pragma unroll
            for (int off = 8; off >= 1; off >>= 1)
                v = fmaxf(v, __shfl_xor_sync(0xffffffffu, v, off, 16));
            float mn = fmaxf(m[i], v);
            float sclf = __expf(m[i] - mn);
            m[i] = mn;
            float s = 0.f;
#pragma unroll
            for (int j = 0; j < 4; j++) {
                float p = __expf(sc[i][j] - mn);
                Ps[(r0 + i) * 68 + tx + (j << 4)] = p;
                s += p;
            }
#pragma unroll
            for (int off = 8; off >= 1; off >>= 1)
                s += __shfl_xor_sync(0xffffffffu, s, off, 16);
            l[i] = l[i] * sclf + s;
            ull sp = pk2(sclf);
#pragma unroll
            for (int j = 0; j < 4; j++) mul2(o2[i][j], sp);
        }
        __syncthreads();

        for (int k = 0; k < 64; k++) {
            ull v2[4];
#pragma unroll
            for (int j = 0; j < 4; j++)
                v2[j] = *(const ull*)&Vs[k * 132 + (tx << 1) + (j << 5)];
#pragma unroll
            for (int i = 0; i < 4; i++) {
                ull pp = pk2(Ps[(r0 + i) * 68 + k]);
#pragma unroll
                for (int j = 0; j < 4; j++) fma2(o2[i][j], pp, v2[j]);
            }
        }
        __syncthreads();
    }

#pragma unroll
    for (int i = 0; i < 4; i++) {
        float inv = 1.0f / l[i];
        float* cp = g_C + (size_t)(tok0 + r0 + i) * HID + head * HDIM + (tx << 1);
#pragma unroll
        for (int j = 0; j < 4; j++) {
            float2 v = unpk(o2[i][j]);
            v.x *= inv; v.y *= inv;
            *(float2*)(cp + (j << 5)) = v;
        }
    }
}

// ---------------- launch ----------------
extern "C" void kernel_launch(void* const* d_in, const int* in_sizes, int n_in,
                              void* d_out, int out_size) {
    const float* X = (const float*)d_in[0];
    // d_in[1] = attention_mask: causal by construction; applied analytically.
    const float* Wq = (const float*)d_in[2];
    const float* Wk = (const float*)d_in[3];
    const float* Wv = (const float*)d_in[4];
    const float* Wo = (const float*)d_in[5];
    float* out = (float*)d_out;

    float *Qb, *Kb, *Vb, *Cb;
    __nv_bfloat16 *Ah, *Al, *Wh, *Wl;
    cudaGetSymbolAddress((void**)&Qb, g_Q);
    cudaGetSymbolAddress((void**)&Kb, g_K);
    cudaGetSymbolAddress((void**)&Vb, g_V);
    cudaGetSymbolAddress((void**)&Cb, g_C);
    cudaGetSymbolAddress((void**)&Ah, g_Ahi);
    cudaGetSymbolAddress((void**)&Al, g_Alo);
    cudaGetSymbolAddress((void**)&Wh, g_Whi);
    cudaGetSymbolAddress((void**)&Wl, g_Wlo);

    cudaFuncSetAttribute(flash_attn_kernel,
                         cudaFuncAttributeMaxDynamicSharedMemorySize, ATTN_SMEM);
    cudaFuncSetAttribute(gemm_hmma,
                         cudaFuncAttributeMaxDynamicSharedMemorySize, GEMM_SMEM);

    const int N4 = TOK * HID / 4;
    const int SB = 256, SG = (N4 + SB - 1) / SB;
    dim3 g(32, 32);

    rope_tables_kernel<<<(SEQ * 64 + 255) / 256, 256>>>();
    split_kernel<<<SG, SB>>>(X, Ah, Al, N4);

    split_kernel<<<SG, SB>>>(Wq, Wh, Wl, N4);
    gemm_hmma<<<g, 512, GEMM_SMEM>>>(Ah, Al, Wh, Wl, Qb);
    split_kernel<<<SG, SB>>>(Wk, Wh, Wl, N4);
    gemm_hmma<<<g, 512, GEMM_SMEM>>>(Ah, Al, Wh, Wl, Kb);
    split_kernel<<<SG, SB>>>(Wv, Wh, Wl, N4);
    gemm_hmma<<<g, 512, GEMM_SMEM>>>(Ah, Al, Wh, Wl, Vb);

    rope_apply_kernel<<<(TOK * NHEAD * 32 + 255) / 256, 256>>>();
    flash_attn_kernel<<<dim3(32, 32, 2), 256, ATTN_SMEM>>>();

    split_kernel<<<SG, SB>>>(Cb, Ah, Al, N4);
    split_kernel<<<SG, SB>>>(Wo, Wh, Wl, N4);
    gemm_hmma<<<g, 512, GEMM_SMEM>>>(Ah, Al, Wh, Wl, out);
}

// round 14
// speedup vs baseline: 1.0247x; 1.0247x over previous
#include <cuda_runtime.h>
#include <cuda_bf16.h>
#include <math.h>
#include <cstdint>

#define TOK 4096      // B*S
#define HID 4096
#define SEQ 2048
#define NHEAD 32
#define HDIM 128

// ---------------- scratch (allocation-free: __device__ globals) ----------------
__device__ float g_Q[TOK * HID];
__device__ float g_K[TOK * HID];
__device__ float g_V[TOK * HID];
__device__ float g_C[TOK * HID];
__device__ float g_cos[SEQ * 64];
__device__ float g_sin[SEQ * 64];
__device__ __nv_bfloat16 g_Ahi[TOK * HID];   // split of X (then of C)
__device__ __nv_bfloat16 g_Alo[TOK * HID];
__device__ __nv_bfloat16 g_Whi[HID * HID];   // split of current weight
__device__ __nv_bfloat16 g_Wlo[HID * HID];

typedef unsigned long long ull;
__device__ __forceinline__ uint32_t smem_u32(const void* p) {
    uint32_t a;
    asm("{ .reg .u64 t; cvta.to.shared.u64 t, %1; cvt.u32.u64 %0, t; }" : "=r"(a) : "l"(p));
    return a;
}
__device__ __forceinline__ void cp16(uint32_t s, const void* g) {
    asm volatile("cp.async.cg.shared.global [%0], [%1], 16;" :: "r"(s), "l"(g));
}
__device__ __forceinline__ void ldsm_x4(uint32_t* r, uint32_t addr) {
    asm volatile("ldmatrix.sync.aligned.m8n8.x4.shared.b16 {%0,%1,%2,%3}, [%4];"
                 : "=r"(r[0]), "=r"(r[1]), "=r"(r[2]), "=r"(r[3]) : "r"(addr));
}
__device__ __forceinline__ void mma_bf16(float* d, const uint32_t* a, const uint32_t* b) {
    asm volatile("mma.sync.aligned.m16n8k16.row.col.f32.bf16.bf16.f32 "
                 "{%0,%1,%2,%3}, {%4,%5,%6,%7}, {%8,%9}, {%0,%1,%2,%3};"
                 : "+f"(d[0]), "+f"(d[1]), "+f"(d[2]), "+f"(d[3])
                 : "r"(a[0]), "r"(a[1]), "r"(a[2]), "r"(a[3]), "r"(b[0]), "r"(b[1]));
}

// ---------------- fp32 split: x -> hi(bf16) + lo(bf16 residual), 4 elem/thread --
__global__ void split_kernel(const float* __restrict__ x,
                             __nv_bfloat16* __restrict__ hi,
                             __nv_bfloat16* __restrict__ lo, int n4) {
    int i = blockIdx.x * blockDim.x + threadIdx.x;
    if (i >= n4) return;
    float4 v = *reinterpret_cast<const float4*>(x + 4 * (size_t)i);
    __nv_bfloat16 h0 = __float2bfloat16(v.x), h1 = __float2bfloat16(v.y);
    __nv_bfloat16 h2 = __float2bfloat16(v.z), h3 = __float2bfloat16(v.w);
    __nv_bfloat162 hp0(h0, h1), hp1(h2, h3);
    __nv_bfloat162 lp0(__float2bfloat16(v.x - __bfloat162float(h0)),
                       __float2bfloat16(v.y - __bfloat162float(h1)));
    __nv_bfloat162 lp1(__float2bfloat16(v.z - __bfloat162float(h2)),
                       __float2bfloat16(v.w - __bfloat162float(h3)));
    *reinterpret_cast<uint2*>(hi + 4 * (size_t)i) =
        make_uint2(*(uint32_t*)&hp0, *(uint32_t*)&hp1);
    *reinterpret_cast<uint2*>(lo + 4 * (size_t)i) =
        make_uint2(*(uint32_t*)&lp0, *(uint32_t*)&lp1);
}

// ---------------- HMMA GEMM: C[t][o] = sum_k A[t][k]*W[o][k] -------------------
// 128x128 CTA tile, BK=64, 8 warps (64x32 each), mma.m16n8k16 bf16.
// Split-3 products reordered into 3 PASSES over 16 accumulators so dependent
// MMAs on the same acc are 16 apart (R13 lesson: back-to-back same-acc MMAs
// serialize the tensor pipe at ~63%).
#define BK 64
#define TPITCH 144                         // bytes per smem row (128 data + 16 pad)
#define TILE_B (128 * TPITCH)              // 18432
#define BUF_B (4 * TILE_B)                 // Ahi,Alo,Bhi,Blo = 73728
#define GEMM_SMEM (2 * BUF_B)              // 147456
#define NKIT (HID / BK)                    // 64
#define NPID 32
#define GROUP_M 12

__global__ __launch_bounds__(256, 1)
void gemm_hmma(const __nv_bfloat16* __restrict__ Ahi, const __nv_bfloat16* __restrict__ Alo,
               const __nv_bfloat16* __restrict__ Bhi, const __nv_bfloat16* __restrict__ Blo,
               float* __restrict__ C) {
    extern __shared__ __align__(128) char smem[];
    const uint32_t smem_base = smem_u32(smem);
    const int tid = threadIdx.x;
    const int wid = tid >> 5, lane = tid & 31;

    // grouped swizzle: consecutive pids walk 12 bm-rows before advancing bn
    const int pid = blockIdx.y * NPID + blockIdx.x;
    const int group_id = pid / (GROUP_M * NPID);
    const int first_m = group_id * GROUP_M;
    const int gsz = (NPID - first_m) < GROUP_M ? (NPID - first_m) : GROUP_M;
    const int bm = (first_m + (pid % gsz)) << 7;
    const int bn = ((pid % (GROUP_M * NPID)) / gsz) << 7;

    const __nv_bfloat16* src[4] = {Ahi + (size_t)bm * HID, Alo + (size_t)bm * HID,
                                   Bhi + (size_t)bn * HID, Blo + (size_t)bn * HID};

    const int m_base = (wid & 1) << 6;     // 0 or 64
    const int n_base = (wid >> 1) << 5;    // 0,32,64,96

    float acc[4][4][4];
#pragma unroll
    for (int mi = 0; mi < 4; mi++)
#pragma unroll
        for (int ni = 0; ni < 4; ni++)
#pragma unroll
            for (int q = 0; q < 4; q++) acc[mi][ni][q] = 0.f;

    // loader: 4096 16B units per chunk (4 tiles x 128 rows x 8 units), 16/thread
#define LOAD_CHUNK(bufsel, k0)                                                   \
    do {                                                                         \
        uint32_t sb = smem_base + (bufsel) * BUF_B;                              \
        _Pragma("unroll")                                                        \
        for (int u = 0; u < 16; u++) {                                           \
            int e = (u << 8) + tid;                                              \
            int t = e >> 10, r = (e >> 3) & 127, q = e & 7;                      \
            cp16(sb + t * TILE_B + r * TPITCH + q * 16,                          \
                 src[t] + (size_t)r * HID + (k0) + q * 8);                       \
        }                                                                        \
    } while (0)

    LOAD_CHUNK(0, 0);
    asm volatile("cp.async.commit_group;");

    // A ldsm.x4: rows m16, two 16B col halves
    const uint32_t aoff = (m_base + (lane & 15)) * TPITCH + ((lane >> 4) << 4);
    // B ldsm.x4: tiles {n0-7,k0-7},{n0-7,k8-15},{n8-15,k0-7},{n8-15,k8-15}
    const uint32_t boff = (n_base + (lane & 7) + (((lane >> 4) & 1) << 3)) * TPITCH +
                          (((lane >> 3) & 1) << 4);

    int buf = 0;
    for (int it = 0; it < NKIT; it++) {
        asm volatile("cp.async.wait_group 0;");
        __syncthreads();
        if (it + 1 < NKIT) {
            LOAD_CHUNK(buf ^ 1, (it + 1) << 6);
            asm volatile("cp.async.commit_group;");
        }

        const uint32_t sA = smem_base + buf * BUF_B;
        const uint32_t sAhi = sA, sAlo = sA + TILE_B;
        const uint32_t sBhi = sA + 2 * TILE_B, sBlo = sA + 3 * TILE_B;
#pragma unroll
        for (int kk = 0; kk < 4; kk++) {   // four k16 steps per 64-chunk
            uint32_t ah[4][4], al[4][4], bh[2][4], bl[2][4];
#pragma unroll
            for (int mi = 0; mi < 4; mi++) {
                ldsm_x4(ah[mi], sAhi + aoff + mi * (16 * TPITCH) + kk * 32);
                ldsm_x4(al[mi], sAlo + aoff + mi * (16 * TPITCH) + kk * 32);
            }
#pragma unroll
            for (int g = 0; g < 2; g++) {  // n16 groups
                ldsm_x4(bh[g], sBhi + boff + g * (16 * TPITCH) + kk * 32);
                ldsm_x4(bl[g], sBlo + boff + g * (16 * TPITCH) + kk * 32);
            }
            // pass 0: Ahi*Bhi over all 16 accs (no same-acc adjacency)
#pragma unroll
            for (int mi = 0; mi < 4; mi++)
#pragma unroll
                for (int ni = 0; ni < 4; ni++)
                    mma_bf16(acc[mi][ni], ah[mi], &bh[ni >> 1][(ni & 1) << 1]);
            // pass 1: Ahi*Blo
#pragma unroll
            for (int mi = 0; mi < 4; mi++)
#pragma unroll
                for (int ni = 0; ni < 4; ni++)
                    mma_bf16(acc[mi][ni], ah[mi], &bl[ni >> 1][(ni & 1) << 1]);
            // pass 2: Alo*Bhi
#pragma unroll
            for (int mi = 0; mi < 4; mi++)
#pragma unroll
                for (int ni = 0; ni < 4; ni++)
                    mma_bf16(acc[mi][ni], al[mi], &bh[ni >> 1][(ni & 1) << 1]);
        }
        buf ^= 1;
    }
#undef LOAD_CHUNK

    // epilogue: standard m16n8 accumulator thread mapping
#pragma unroll
    for (int mi = 0; mi < 4; mi++)
#pragma unroll
        for (int ni = 0; ni < 4; ni++) {
            int row = bm + m_base + mi * 16 + (lane >> 2);
            int col = bn + n_base + ni * 8 + ((lane & 3) << 1);
            *(float2*)&C[(size_t)row * HID + col] =
                make_float2(acc[mi][ni][0], acc[mi][ni][1]);
            *(float2*)&C[(size_t)(row + 8) * HID + col] =
                make_float2(acc[mi][ni][2], acc[mi][ni][3]);
        }
}

// ---------------- RoPE tables (double precision) -------------------------------
__global__ void rope_tables_kernel() {
    int i = blockIdx.x * blockDim.x + threadIdx.x;
    if (i >= SEQ * 64) return;
    int d = i & 63, s = i >> 6;
    double inv = exp(-((double)d / 64.0) * 9.210340371976184);  // ln(10000)
    double ang = (double)s * inv;
    g_cos[i] = (float)cos(ang);
    g_sin[i] = (float)sin(ang);
}

// ---------------- RoPE apply (in-place on Q and K), float2-vectorized ----------
__global__ void rope_apply_kernel() {
    int idx = blockIdx.x * blockDim.x + threadIdx.x;
    if (idx >= TOK * NHEAD * 32) return;
    int dp = (idx & 31) << 1;
    int head = (idx >> 5) & 31;
    int t = idx >> 10;
    int s = t & (SEQ - 1);
    float2 c = *(const float2*)&g_cos[(s << 6) + dp];
    float2 sn = *(const float2*)&g_sin[(s << 6) + dp];
    float* qp = g_Q + (size_t)t * HID + head * HDIM + dp;
    float* kp = g_K + (size_t)t * HID + head * HDIM + dp;
    float2 q1 = *(float2*)qp, q2 = *(float2*)(qp + 64);
    *(float2*)qp = make_float2(q1.x * c.x - q2.x * sn.x, q1.y * c.y - q2.y * sn.y);
    *(float2*)(qp + 64) = make_float2(q2.x * c.x + q1.x * sn.x, q2.y * c.y + q1.y * sn.y);
    float2 k1 = *(float2*)kp, k2 = *(float2*)(kp + 64);
    *(float2*)kp = make_float2(k1.x * c.x - k2.x * sn.x, k1.y * c.y - k2.y * sn.y);
    *(float2*)(kp + 64) = make_float2(k2.x * c.x + k1.x * sn.x, k2.y * c.y + k1.y * sn.y);
}

// ---------------- packed f32x2 helpers ----------------
__device__ __forceinline__ ull pk2(float x) {
    ull r; asm("mov.b64 %0, {%1, %1};" : "=l"(r) : "f"(x)); return r;
}
__device__ __forceinline__ float2 unpk(ull u) {
    float2 r; asm("mov.b64 {%0, %1}, %2;" : "=f"(r.x), "=f"(r.y) : "l"(u)); return r;
}
__device__ __forceinline__ void fma2(ull& d, ull a, ull b) {
    asm("fma.rn.f32x2 %0, %1, %2, %0;" : "+l"(d) : "l"(a), "l"(b));
}
__device__ __forceinline__ void mul2(ull& d, ull s) {
    asm("mul.rn.f32x2 %0, %0, %1;" : "+l"(d) : "l"(s));
}

// ---------------- Flash attention (causal, fp32, online softmax) ---------------
#define ATTN_SMEM (3 * 64 * 132 * 4)

__global__ __launch_bounds__(256, 2)
void flash_attn_kernel() {
    extern __shared__ __align__(16) float sm[];
    float* Qs = sm;
    float* Ks = sm + 64 * 132;
    float* Vs = sm + 2 * 64 * 132;
    float* Ps = Ks;   // overlay on Ks (K dead post-QK^T)

    const int qi = 31 - blockIdx.x;  // LPT
    const int head = blockIdx.y, b = blockIdx.z;
    const int tid = threadIdx.x;
    const int tx = tid & 15, ty = tid >> 4;
    const int r0 = ty << 2;
    const int tok0 = (b << 11) + (qi << 6);

    const float* Qg = g_Q + (size_t)tok0 * HID + head * HDIM;
    for (int f = tid; f < 64 * 32; f += 256) {
        int row = f >> 5, c4 = (f & 31) << 2;
        *(float4*)&Qs[row * 132 + c4] = *(const float4*)(Qg + (size_t)row * HID + c4);
    }

    float m[4], l[4];
    ull o2[4][4];
#pragma unroll
    for (int i = 0; i < 4; i++) {
        m[i] = -1e30f; l[i] = 0.f;
#pragma unroll
        for (int j = 0; j < 4; j++) o2[i][j] = 0ull;
    }
    __syncthreads();

    const float scale = 0.08838834764831845f;
    for (int kt = 0; kt <= qi; kt++) {
        const size_t kvoff = (size_t)((b << 11) + (kt << 6)) * HID + head * HDIM;
        for (int f = tid; f < 64 * 32; f += 256) {
            int row = f >> 5, c4 = (f & 31) << 2;
            *(float4*)&Ks[row * 132 + c4] = *(const float4*)(g_K + kvoff + (size_t)row * HID + c4);
            *(float4*)&Vs[row * 132 + c4] = *(const float4*)(g_V + kvoff + (size_t)row * HID + c4);
        }
        __syncthreads();

        ull s2[4][4];
#pragma unroll
        for (int i = 0; i < 4; i++)
#pragma unroll
            for (int j = 0; j < 4; j++) s2[i][j] = 0ull;

        for (int kk = 0; kk < 128; kk += 2) {
            ull qa[4], kb[4];
#pragma unroll
            for (int i = 0; i < 4; i++) qa[i] = *(const ull*)&Qs[(r0 + i) * 132 + kk];
#pragma unroll
            for (int j = 0; j < 4; j++) kb[j] = *(const ull*)&Ks[(tx + (j << 4)) * 132 + kk];
#pragma unroll
            for (int i = 0; i < 4; i++)
#pragma unroll
                for (int j = 0; j < 4; j++) fma2(s2[i][j], qa[i], kb[j]);
        }
        float sc[4][4];
#pragma unroll
        for (int i = 0; i < 4; i++)
#pragma unroll
            for (int j = 0; j < 4; j++) {
                float2 p = unpk(s2[i][j]);
                sc[i][j] = (p.x + p.y) * scale;
            }
        if (kt == qi) {
#pragma unroll
            for (int i = 0; i < 4; i++)
#pragma unroll
                for (int j = 0; j < 4; j++)
                    if (tx + (j << 4) > r0 + i) sc[i][j] = -1e9f;
        }
        __syncthreads();

#pragma unroll
        for (int i = 0; i < 4; i++) {
            float v = fmaxf(fmaxf(sc[i][0], sc[i][1]), fmaxf(sc[i][2], sc[i][3]));
#pragma unroll
            for (int off = 8; off >= 1; off >>= 1)
                v = fmaxf(v, __shfl_xor_sync(0xffffffffu, v, off, 16));
            float mn = fmaxf(m[i], v);
            float sclf = __expf(m[i] - mn);
            m[i] = mn;
            float s = 0.f;
#pragma unroll
            for (int j = 0; j < 4; j++) {
                float p = __expf(sc[i][j] - mn);
                Ps[(r0 + i) * 68 + tx + (j << 4)] = p;
                s += p;
            }
#pragma unroll
            for (int off = 8; off >= 1; off >>= 1)
                s += __shfl_xor_sync(0xffffffffu, s, off, 16);
            l[i] = l[i] * sclf + s;
            ull sp = pk2(sclf);
#pragma unroll
            for (int j = 0; j < 4; j++) mul2(o2[i][j], sp);
        }
        __syncthreads();

        for (int k = 0; k < 64; k++) {
            ull v2[4];
#pragma unroll
            for (int j = 0; j < 4; j++)
                v2[j] = *(const ull*)&Vs[k * 132 + (tx << 1) + (j << 5)];
#pragma unroll
            for (int i = 0; i < 4; i++) {
                ull pp = pk2(Ps[(r0 + i) * 68 + k]);
#pragma unroll
                for (int j = 0; j < 4; j++) fma2(o2[i][j], pp, v2[j]);
            }
        }
        __syncthreads();
    }

#pragma unroll
    for (int i = 0; i < 4; i++) {
        float inv = 1.0f / l[i];
        float* cp = g_C + (size_t)(tok0 + r0 + i) * HID + head * HDIM + (tx << 1);
#pragma unroll
        for (int j = 0; j < 4; j++) {
            float2 v = unpk(o2[i][j]);
            v.x *= inv; v.y *= inv;
            *(float2*)(cp + (j << 5)) = v;
        }
    }
}

// ---------------- launch ----------------
extern "C" void kernel_launch(void* const* d_in, const int* in_sizes, int n_in,
                              void* d_out, int out_size) {
    const float* X = (const float*)d_in[0];
    // d_in[1] = attention_mask: causal by construction; applied analytically.
    const float* Wq = (const float*)d_in[2];
    const float* Wk = (const float*)d_in[3];
    const float* Wv = (const float*)d_in[4];
    const float* Wo = (const float*)d_in[5];
    float* out = (float*)d_out;

    float *Qb, *Kb, *Vb, *Cb;
    __nv_bfloat16 *Ah, *Al, *Wh, *Wl;
    cudaGetSymbolAddress((void**)&Qb, g_Q);
    cudaGetSymbolAddress((void**)&Kb, g_K);
    cudaGetSymbolAddress((void**)&Vb, g_V);
    cudaGetSymbolAddress((void**)&Cb, g_C);
    cudaGetSymbolAddress((void**)&Ah, g_Ahi);
    cudaGetSymbolAddress((void**)&Al, g_Alo);
    cudaGetSymbolAddress((void**)&Wh, g_Whi);
    cudaGetSymbolAddress((void**)&Wl, g_Wlo);

    cudaFuncSetAttribute(flash_attn_kernel,
                         cudaFuncAttributeMaxDynamicSharedMemorySize, ATTN_SMEM);
    cudaFuncSetAttribute(gemm_hmma,
                         cudaFuncAttributeMaxDynamicSharedMemorySize, GEMM_SMEM);

    const int N4 = TOK * HID / 4;
    const int SB = 256, SG = (N4 + SB - 1) / SB;
    dim3 g(32, 32);

    rope_tables_kernel<<<(SEQ * 64 + 255) / 256, 256>>>();
    split_kernel<<<SG, SB>>>(X, Ah, Al, N4);

    split_kernel<<<SG, SB>>>(Wq, Wh, Wl, N4);
    gemm_hmma<<<g, 256, GEMM_SMEM>>>(Ah, Al, Wh, Wl, Qb);
    split_kernel<<<SG, SB>>>(Wk, Wh, Wl, N4);
    gemm_hmma<<<g, 256, GEMM_SMEM>>>(Ah, Al, Wh, Wl, Kb);
    split_kernel<<<SG, SB>>>(Wv, Wh, Wl, N4);
    gemm_hmma<<<g, 256, GEMM_SMEM>>>(Ah, Al, Wh, Wl, Vb);

    rope_apply_kernel<<<(TOK * NHEAD * 32 + 255) / 256, 256>>>();
    flash_attn_kernel<<<dim3(32, 32, 2), 256, ATTN_SMEM>>>();

    split_kernel<<<SG, SB>>>(Cb, Ah, Al, N4);
    split_kernel<<<SG, SB>>>(Wo, Wh, Wl, N4);
    gemm_hmma<<<g, 256, GEMM_SMEM>>>(Ah, Al, Wh, Wl, out);
}

// round 15
// speedup vs baseline: 1.0301x; 1.0052x over previous
#include <cuda_runtime.h>
#include <cuda_bf16.h>
#include <math.h>
#include <cstdint>

#define TOK 4096      // B*S
#define HID 4096
#define SEQ 2048
#define NHEAD 32
#define HDIM 128

// ---------------- scratch (allocation-free: __device__ globals) ----------------
__device__ float g_QKV[3 * TOK * HID];          // Q | K | V
__device__ float g_cos[SEQ * 64];
__device__ float g_sin[SEQ * 64];
__device__ __nv_bfloat16 g_Ahi[TOK * HID];      // split of X, then of attn output
__device__ __nv_bfloat16 g_Alo[TOK * HID];
__device__ __nv_bfloat16 g_Whi[4 * HID * HID];  // Wq|Wk|Wv|Wo hi
__device__ __nv_bfloat16 g_Wlo[4 * HID * HID];  // Wq|Wk|Wv|Wo lo

typedef unsigned long long ull;
__device__ __forceinline__ uint32_t smem_u32(const void* p) {
    uint32_t a;
    asm("{ .reg .u64 t; cvta.to.shared.u64 t, %1; cvt.u32.u64 %0, t; }" : "=r"(a) : "l"(p));
    return a;
}
__device__ __forceinline__ void cp16(uint32_t s, const void* g) {
    asm volatile("cp.async.cg.shared.global [%0], [%1], 16;" :: "r"(s), "l"(g));
}
__device__ __forceinline__ void ldsm_x4(uint32_t* r, uint32_t addr) {
    asm volatile("ldmatrix.sync.aligned.m8n8.x4.shared.b16 {%0,%1,%2,%3}, [%4];"
                 : "=r"(r[0]), "=r"(r[1]), "=r"(r[2]), "=r"(r[3]) : "r"(addr));
}
__device__ __forceinline__ void mma_bf16(float* d, const uint32_t* a, const uint32_t* b) {
    asm volatile("mma.sync.aligned.m16n8k16.row.col.f32.bf16.bf16.f32 "
                 "{%0,%1,%2,%3}, {%4,%5,%6,%7}, {%8,%9}, {%0,%1,%2,%3};"
                 : "+f"(d[0]), "+f"(d[1]), "+f"(d[2]), "+f"(d[3])
                 : "r"(a[0]), "r"(a[1]), "r"(a[2]), "r"(a[3]), "r"(b[0]), "r"(b[1]));
}

// ---------------- fp32 split: x -> hi(bf16) + lo(bf16 residual), 4 elem/thread --
__device__ __forceinline__ void split4(const float* __restrict__ x,
                                       __nv_bfloat16* __restrict__ hi,
                                       __nv_bfloat16* __restrict__ lo, int i) {
    float4 v = *reinterpret_cast<const float4*>(x + 4 * (size_t)i);
    __nv_bfloat16 h0 = __float2bfloat16(v.x), h1 = __float2bfloat16(v.y);
    __nv_bfloat16 h2 = __float2bfloat16(v.z), h3 = __float2bfloat16(v.w);
    __nv_bfloat162 hp0(h0, h1), hp1(h2, h3);
    __nv_bfloat162 lp0(__float2bfloat16(v.x - __bfloat162float(h0)),
                       __float2bfloat16(v.y - __bfloat162float(h1)));
    __nv_bfloat162 lp1(__float2bfloat16(v.z - __bfloat162float(h2)),
                       __float2bfloat16(v.w - __bfloat162float(h3)));
    *reinterpret_cast<uint2*>(hi + 4 * (size_t)i) =
        make_uint2(*(uint32_t*)&hp0, *(uint32_t*)&hp1);
    *reinterpret_cast<uint2*>(lo + 4 * (size_t)i) =
        make_uint2(*(uint32_t*)&lp0, *(uint32_t*)&lp1);
}

__global__ void split_kernel(const float* __restrict__ x,
                             __nv_bfloat16* __restrict__ hi,
                             __nv_bfloat16* __restrict__ lo, int n4) {
    int i = blockIdx.x * blockDim.x + threadIdx.x;
    if (i >= n4) return;
    split4(x, hi, lo, i);
}

// all 4 weights in one launch; blockIdx.y selects the source
__global__ void split_w_kernel(const float* __restrict__ w0, const float* __restrict__ w1,
                               const float* __restrict__ w2, const float* __restrict__ w3,
                               __nv_bfloat16* __restrict__ hi,
                               __nv_bfloat16* __restrict__ lo, int n4) {
    int i = blockIdx.x * blockDim.x + threadIdx.x;
    if (i >= n4) return;
    int z = blockIdx.y;
    const float* w = (z == 0) ? w0 : (z == 1) ? w1 : (z == 2) ? w2 : w3;
    split4(w, hi + (size_t)z * HID * HID, lo + (size_t)z * HID * HID, i);
}

// ---------------- HMMA GEMM: C[t][o] = sum_k A[t][k]*W[o][k] -------------------
// 128x128 CTA tile, BK=64, 8 warps, mma.m16n8k16 bf16, split-3 in 3 passes.
// blockIdx.z selects weight slice (z*HID*HID) and output slice (z*TOK*HID):
// QKV batched in one launch (merges wave tails, shares A panels in L2).
#define BK 64
#define TPITCH 144
#define TILE_B (128 * TPITCH)
#define BUF_B (4 * TILE_B)
#define GEMM_SMEM (2 * BUF_B)              // 147456
#define NKIT (HID / BK)                    // 64
#define NPID 32
#define GROUP_M 12

__global__ __launch_bounds__(256, 1)
void gemm_hmma(const __nv_bfloat16* __restrict__ Ahi, const __nv_bfloat16* __restrict__ Alo,
               const __nv_bfloat16* __restrict__ Bhi, const __nv_bfloat16* __restrict__ Blo,
               float* __restrict__ C) {
    extern __shared__ __align__(128) char smem[];
    const uint32_t smem_base = smem_u32(smem);
    const int tid = threadIdx.x;
    const int wid = tid >> 5, lane = tid & 31;

    const size_t zW = (size_t)blockIdx.z * HID * HID;
    C += (size_t)blockIdx.z * TOK * HID;

    const int pid = blockIdx.y * NPID + blockIdx.x;
    const int group_id = pid / (GROUP_M * NPID);
    const int first_m = group_id * GROUP_M;
    const int gsz = (NPID - first_m) < GROUP_M ? (NPID - first_m) : GROUP_M;
    const int bm = (first_m + (pid % gsz)) << 7;
    const int bn = ((pid % (GROUP_M * NPID)) / gsz) << 7;

    const __nv_bfloat16* src[4] = {Ahi + (size_t)bm * HID, Alo + (size_t)bm * HID,
                                   Bhi + zW + (size_t)bn * HID, Blo + zW + (size_t)bn * HID};

    const int m_base = (wid & 1) << 6;     // 0 or 64
    const int n_base = (wid >> 1) << 5;    // 0,32,64,96

    float acc[4][4][4];
#pragma unroll
    for (int mi = 0; mi < 4; mi++)
#pragma unroll
        for (int ni = 0; ni < 4; ni++)
#pragma unroll
            for (int q = 0; q < 4; q++) acc[mi][ni][q] = 0.f;

#define LOAD_CHUNK(bufsel, k0)                                                   \
    do {                                                                         \
        uint32_t sb = smem_base + (bufsel) * BUF_B;                              \
        _Pragma("unroll")                                                        \
        for (int u = 0; u < 16; u++) {                                           \
            int e = (u << 8) + tid;                                              \
            int t = e >> 10, r = (e >> 3) & 127, q = e & 7;                      \
            cp16(sb + t * TILE_B + r * TPITCH + q * 16,                          \
                 src[t] + (size_t)r * HID + (k0) + q * 8);                       \
        }                                                                        \
    } while (0)

    LOAD_CHUNK(0, 0);
    asm volatile("cp.async.commit_group;");

    const uint32_t aoff = (m_base + (lane & 15)) * TPITCH + ((lane >> 4) << 4);
    const uint32_t boff = (n_base + (lane & 7) + (((lane >> 4) & 1) << 3)) * TPITCH +
                          (((lane >> 3) & 1) << 4);

    int buf = 0;
    for (int it = 0; it < NKIT; it++) {
        asm volatile("cp.async.wait_group 0;");
        __syncthreads();
        if (it + 1 < NKIT) {
            LOAD_CHUNK(buf ^ 1, (it + 1) << 6);
            asm volatile("cp.async.commit_group;");
        }

        const uint32_t sA = smem_base + buf * BUF_B;
        const uint32_t sAhi = sA, sAlo = sA + TILE_B;
        const uint32_t sBhi = sA + 2 * TILE_B, sBlo = sA + 3 * TILE_B;
#pragma unroll
        for (int kk = 0; kk < 4; kk++) {
            uint32_t ah[4][4], al[4][4], bh[2][4], bl[2][4];
#pragma unroll
            for (int mi = 0; mi < 4; mi++) {
                ldsm_x4(ah[mi], sAhi + aoff + mi * (16 * TPITCH) + kk * 32);
                ldsm_x4(al[mi], sAlo + aoff + mi * (16 * TPITCH) + kk * 32);
            }
#pragma unroll
            for (int g = 0; g < 2; g++) {
                ldsm_x4(bh[g], sBhi + boff + g * (16 * TPITCH) + kk * 32);
                ldsm_x4(bl[g], sBlo + boff + g * (16 * TPITCH) + kk * 32);
            }
#pragma unroll
            for (int mi = 0; mi < 4; mi++)
#pragma unroll
                for (int ni = 0; ni < 4; ni++)
                    mma_bf16(acc[mi][ni], ah[mi], &bh[ni >> 1][(ni & 1) << 1]);
#pragma unroll
            for (int mi = 0; mi < 4; mi++)
#pragma unroll
                for (int ni = 0; ni < 4; ni++)
                    mma_bf16(acc[mi][ni], ah[mi], &bl[ni >> 1][(ni & 1) << 1]);
#pragma unroll
            for (int mi = 0; mi < 4; mi++)
#pragma unroll
                for (int ni = 0; ni < 4; ni++)
                    mma_bf16(acc[mi][ni], al[mi], &bh[ni >> 1][(ni & 1) << 1]);
        }
        buf ^= 1;
    }
#undef LOAD_CHUNK

#pragma unroll
    for (int mi = 0; mi < 4; mi++)
#pragma unroll
        for (int ni = 0; ni < 4; ni++) {
            int row = bm + m_base + mi * 16 + (lane >> 2);
            int col = bn + n_base + ni * 8 + ((lane & 3) << 1);
            *(float2*)&C[(size_t)row * HID + col] =
                make_float2(acc[mi][ni][0], acc[mi][ni][1]);
            *(float2*)&C[(size_t)(row + 8) * HID + col] =
                make_float2(acc[mi][ni][2], acc[mi][ni][3]);
        }
}

// ---------------- RoPE tables (double precision) -------------------------------
__global__ void rope_tables_kernel() {
    int i = blockIdx.x * blockDim.x + threadIdx.x;
    if (i >= SEQ * 64) return;
    int d = i & 63, s = i >> 6;
    double inv = exp(-((double)d / 64.0) * 9.210340371976184);  // ln(10000)
    double ang = (double)s * inv;
    g_cos[i] = (float)cos(ang);
    g_sin[i] = (float)sin(ang);
}

// ---------------- RoPE apply (in-place on Q and K), float2-vectorized ----------
__global__ void rope_apply_kernel() {
    int idx = blockIdx.x * blockDim.x + threadIdx.x;
    if (idx >= TOK * NHEAD * 32) return;
    int dp = (idx & 31) << 1;
    int head = (idx >> 5) & 31;
    int t = idx >> 10;
    int s = t & (SEQ - 1);
    float2 c = *(const float2*)&g_cos[(s << 6) + dp];
    float2 sn = *(const float2*)&g_sin[(s << 6) + dp];
    float* qp = g_QKV + (size_t)t * HID + head * HDIM + dp;
    float* kp = qp + (size_t)TOK * HID;
    float2 q1 = *(float2*)qp, q2 = *(float2*)(qp + 64);
    *(float2*)qp = make_float2(q1.x * c.x - q2.x * sn.x, q1.y * c.y - q2.y * sn.y);
    *(float2*)(qp + 64) = make_float2(q2.x * c.x + q1.x * sn.x, q2.y * c.y + q1.y * sn.y);
    float2 k1 = *(float2*)kp, k2 = *(float2*)(kp + 64);
    *(float2*)kp = make_float2(k1.x * c.x - k2.x * sn.x, k1.y * c.y - k2.y * sn.y);
    *(float2*)(kp + 64) = make_float2(k2.x * c.x + k1.x * sn.x, k2.y * c.y + k1.y * sn.y);
}

// ---------------- packed f32x2 helpers ----------------
__device__ __forceinline__ ull pk2(float x) {
    ull r; asm("mov.b64 %0, {%1, %1};" : "=l"(r) : "f"(x)); return r;
}
__device__ __forceinline__ float2 unpk(ull u) {
    float2 r; asm("mov.b64 {%0, %1}, %2;" : "=f"(r.x), "=f"(r.y) : "l"(u)); return r;
}
__device__ __forceinline__ void fma2(ull& d, ull a, ull b) {
    asm("fma.rn.f32x2 %0, %1, %2, %0;" : "+l"(d) : "l"(a), "l"(b));
}
__device__ __forceinline__ void mul2(ull& d, ull s) {
    asm("mul.rn.f32x2 %0, %0, %1;" : "+l"(d) : "l"(s));
}

// ---------------- Flash attention (causal, fp32, online softmax) ---------------
// Epilogue writes hi/lo bf16 split directly (fuses the C-split kernel).
#define ATTN_SMEM (3 * 64 * 132 * 4)

__global__ __launch_bounds__(256, 2)
void flash_attn_kernel() {
    extern __shared__ __align__(16) float sm[];
    float* Qs = sm;
    float* Ks = sm + 64 * 132;
    float* Vs = sm + 2 * 64 * 132;
    float* Ps = Ks;   // overlay on Ks (K dead post-QK^T)

    const int qi = 31 - blockIdx.x;  // LPT
    const int head = blockIdx.y, b = blockIdx.z;
    const int tid = threadIdx.x;
    const int tx = tid & 15, ty = tid >> 4;
    const int r0 = ty << 2;
    const int tok0 = (b << 11) + (qi << 6);

    const float* Qg = g_QKV + (size_t)tok0 * HID + head * HDIM;
    for (int f = tid; f < 64 * 32; f += 256) {
        int row = f >> 5, c4 = (f & 31) << 2;
        *(float4*)&Qs[row * 132 + c4] = *(const float4*)(Qg + (size_t)row * HID + c4);
    }

    float m[4], l[4];
    ull o2[4][4];
#pragma unroll
    for (int i = 0; i < 4; i++) {
        m[i] = -1e30f; l[i] = 0.f;
#pragma unroll
        for (int j = 0; j < 4; j++) o2[i][j] = 0ull;
    }
    __syncthreads();

    const float scale = 0.08838834764831845f;
    for (int kt = 0; kt <= qi; kt++) {
        const size_t kvoff = (size_t)((b << 11) + (kt << 6)) * HID + head * HDIM;
        const float* Kg = g_QKV + (size_t)TOK * HID + kvoff;
        const float* Vg = g_QKV + 2 * (size_t)TOK * HID + kvoff;
        for (int f = tid; f < 64 * 32; f += 256) {
            int row = f >> 5, c4 = (f & 31) << 2;
            *(float4*)&Ks[row * 132 + c4] = *(const float4*)(Kg + (size_t)row * HID + c4);
            *(float4*)&Vs[row * 132 + c4] = *(const float4*)(Vg + (size_t)row * HID + c4);
        }
        __syncthreads();

        ull s2[4][4];
#pragma unroll
        for (int i = 0; i < 4; i++)
#pragma unroll
            for (int j = 0; j < 4; j++) s2[i][j] = 0ull;

        for (int kk = 0; kk < 128; kk += 2) {
            ull qa[4], kb[4];
#pragma unroll
            for (int i = 0; i < 4; i++) qa[i] = *(const ull*)&Qs[(r0 + i) * 132 + kk];
#pragma unroll
            for (int j = 0; j < 4; j++) kb[j] = *(const ull*)&Ks[(tx + (j << 4)) * 132 + kk];
#pragma unroll
            for (int i = 0; i < 4; i++)
#pragma unroll
                for (int j = 0; j < 4; j++) fma2(s2[i][j], qa[i], kb[j]);
        }
        float sc[4][4];
#pragma unroll
        for (int i = 0; i < 4; i++)
#pragma unroll
            for (int j = 0; j < 4; j++) {
                float2 p = unpk(s2[i][j]);
                sc[i][j] = (p.x + p.y) * scale;
            }
        if (kt == qi) {
#pragma unroll
            for (int i = 0; i < 4; i++)
#pragma unroll
                for (int j = 0; j < 4; j++)
                    if (tx + (j << 4) > r0 + i) sc[i][j] = -1e9f;
        }
        __syncthreads();

#pragma unroll
        for (int i = 0; i < 4; i++) {
            float v = fmaxf(fmaxf(sc[i][0], sc[i][1]), fmaxf(sc[i][2], sc[i][3]));
#pragma unroll
            for (int off = 8; off >= 1; off >>= 1)
                v = fmaxf(v, __shfl_xor_sync(0xffffffffu, v, off, 16));
            float mn = fmaxf(m[i], v);
            float sclf = __expf(m[i] - mn);
            m[i] = mn;
            float s = 0.f;
#pragma unroll
            for (int j = 0; j < 4; j++) {
                float p = __expf(sc[i][j] - mn);
                Ps[(r0 + i) * 68 + tx + (j << 4)] = p;
                s += p;
            }
#pragma unroll
            for (int off = 8; off >= 1; off >>= 1)
                s += __shfl_xor_sync(0xffffffffu, s, off, 16);
            l[i] = l[i] * sclf + s;
            ull sp = pk2(sclf);
#pragma unroll
            for (int j = 0; j < 4; j++) mul2(o2[i][j], sp);
        }
        __syncthreads();

        for (int k = 0; k < 64; k++) {
            ull v2[4];
#pragma unroll
            for (int j = 0; j < 4; j++)
                v2[j] = *(const ull*)&Vs[k * 132 + (tx << 1) + (j << 5)];
#pragma unroll
            for (int i = 0; i < 4; i++) {
                ull pp = pk2(Ps[(r0 + i) * 68 + k]);
#pragma unroll
                for (int j = 0; j < 4; j++) fma2(o2[i][j], pp, v2[j]);
            }
        }
        __syncthreads();
    }

    // epilogue: normalize and write hi/lo bf16 split directly (for out-proj GEMM)
#pragma unroll
    for (int i = 0; i < 4; i++) {
        float inv = 1.0f / l[i];
        size_t base = (size_t)(tok0 + r0 + i) * HID + head * HDIM + (tx << 1);
#pragma unroll
        for (int j = 0; j < 4; j++) {
            float2 v = unpk(o2[i][j]);
            v.x *= inv; v.y *= inv;
            __nv_bfloat16 h0 = __float2bfloat16(v.x), h1 = __float2bfloat16(v.y);
            __nv_bfloat162 hp(h0, h1);
            __nv_bfloat162 lp(__float2bfloat16(v.x - __bfloat162float(h0)),
                              __float2bfloat16(v.y - __bfloat162float(h1)));
            *reinterpret_cast<uint32_t*>(g_Ahi + base + (j << 5)) = *(uint32_t*)&hp;
            *reinterpret_cast<uint32_t*>(g_Alo + base + (j << 5)) = *(uint32_t*)&lp;
        }
    }
}

// ---------------- launch ----------------
extern "C" void kernel_launch(void* const* d_in, const int* in_sizes, int n_in,
                              void* d_out, int out_size) {
    const float* X = (const float*)d_in[0];
    // d_in[1] = attention_mask: causal by construction; applied analytically.
    const float* Wq = (const float*)d_in[2];
    const float* Wk = (const float*)d_in[3];
    const float* Wv = (const float*)d_in[4];
    const float* Wo = (const float*)d_in[5];
    float* out = (float*)d_out;

    float* QKVb;
    __nv_bfloat16 *Ah, *Al, *Wh, *Wl;
    cudaGetSymbolAddress((void**)&QKVb, g_QKV);
    cudaGetSymbolAddress((void**)&Ah, g_Ahi);
    cudaGetSymbolAddress((void**)&Al, g_Alo);
    cudaGetSymbolAddress((void**)&Wh, g_Whi);
    cudaGetSymbolAddress((void**)&Wl, g_Wlo);

    cudaFuncSetAttribute(flash_attn_kernel,
                         cudaFuncAttributeMaxDynamicSharedMemorySize, ATTN_SMEM);
    cudaFuncSetAttribute(gemm_hmma,
                         cudaFuncAttributeMaxDynamicSharedMemorySize, GEMM_SMEM);

    const int N4 = TOK * HID / 4;
    const int SB = 256, SG = (N4 + SB - 1) / SB;

    rope_tables_kernel<<<(SEQ * 64 + 255) / 256, 256>>>();
    split_kernel<<<SG, SB>>>(X, Ah, Al, N4);
    split_w_kernel<<<dim3(SG, 4), SB>>>(Wq, Wk, Wv, Wo, Wh, Wl, N4);

    gemm_hmma<<<dim3(32, 32, 3), 256, GEMM_SMEM>>>(Ah, Al, Wh, Wl, QKVb);

    rope_apply_kernel<<<(TOK * NHEAD * 32 + 255) / 256, 256>>>();
    flash_attn_kernel<<<dim3(32, 32, 2), 256, ATTN_SMEM>>>();

    gemm_hmma<<<dim3(32, 32, 1), 256, GEMM_SMEM>>>(
        Ah, Al, Wh + 3 * (size_t)HID * HID, Wl + 3 * (size_t)HID * HID, out);
}